// round 4
// baseline (speedup 1.0000x reference)
#include <cuda_runtime.h>

#define N_  256
#define P_  5
#define H_  32
#define B_  256
#define K_  1280            // N_*P_
#define THRESH_ 0.01f

#define SPLITK 16
#define KC 80               // K per split chunk
#define KT 16               // inner k tile

#define EFFW_IT (N_ * K_ / 4)     // 81920 float4 items
#define ACT_IT  (B_ * K_ / 4)     // 81920
#define FLAT_BLOCKS ((EFFW_IT + ACT_IT) / 256)   // 640
#define WT_BLOCKS 8

// ---- scratch (static device globals; no runtime allocation) ----
__device__ float g_act[B_ * K_];          // act[b][j*5+p]
__device__ float g_effw[N_ * K_];         // eff(i,j)*w_pw[i][j][p]
__device__ float g_bias[N_];
__device__ float g_W1t[H_ * N_];          // [k][i]
__device__ float g_b1t[H_ * N_];
__device__ float g_W2t[2 * H_ * N_];      // [(c*32+h)][i]
__device__ float g_b2t[2 * N_];
__device__ float g_part[SPLITK][B_ * N_]; // split-K partials [s][b][i]

// ---------------------------------------------------------------
// prep: fully flat, one float4 of output per thread, no dependent loops.
// ---------------------------------------------------------------
__global__ __launch_bounds__(256)
void prep_kernel(const float* __restrict__ x,
                 const float* __restrict__ adj,
                 const float* __restrict__ bp,
                 const float* __restrict__ w_pw,
                 const float* __restrict__ W1,
                 const float* __restrict__ b1,
                 const float* __restrict__ W2,
                 const float* __restrict__ b2)
{
    const int gid = blockIdx.x * 256 + threadIdx.x;

    if (gid < EFFW_IT) {
        // ---- effw[i][jk..jk+3] = eff(i,j(jk)) * w_pw ----
        const int i  = gid / (K_ / 4);
        const int jk = (gid % (K_ / 4)) * 4;
        float4 w = *reinterpret_cast<const float4*>(w_pw + (size_t)i * K_ + jk);
        const int j0 = (jk    ) / P_;
        const int j1 = (jk + 1) / P_;
        const int j2 = (jk + 2) / P_;
        const int j3 = (jk + 3) / P_;
        float e0 = adj[j0 * N_ + i];
        float e1 = adj[j1 * N_ + i];
        float e2 = adj[j2 * N_ + i];
        float e3 = adj[j3 * N_ + i];
        w.x *= (e0 > THRESH_ && i != j0) ? e0 : 0.f;
        w.y *= (e1 > THRESH_ && i != j1) ? e1 : 0.f;
        w.z *= (e2 > THRESH_ && i != j2) ? e2 : 0.f;
        w.w *= (e3 > THRESH_ && i != j3) ? e3 : 0.f;
        *reinterpret_cast<float4*>(g_effw + (size_t)i * K_ + jk) = w;
    } else if (gid < EFFW_IT + ACT_IT) {
        // ---- act[b][jk..jk+3] = relu(x[b,j] - bp[jk]) ----
        const int idx = gid - EFFW_IT;
        const int b  = idx / (K_ / 4);
        const int jk = (idx % (K_ / 4)) * 4;
        float4 t = *reinterpret_cast<const float4*>(bp + jk);
        const int j0 = (jk    ) / P_;
        const int j1 = (jk + 1) / P_;
        const int j2 = (jk + 2) / P_;
        const int j3 = (jk + 3) / P_;
        const float* xr = x + (size_t)b * N_;
        float4 a;
        a.x = fmaxf(xr[j0] - t.x, 0.f);
        a.y = fmaxf(xr[j1] - t.y, 0.f);
        a.z = fmaxf(xr[j2] - t.z, 0.f);
        a.w = fmaxf(xr[j3] - t.w, 0.f);
        *reinterpret_cast<float4*>(g_act + (size_t)b * K_ + jk) = a;
    } else {
        // ---- transpose MLP params (2048 threads, grid-stride) ----
        const int t = gid - (EFFW_IT + ACT_IT);
        const int NT = WT_BLOCKS * 256;
        for (int idx = t; idx < H_ * N_; idx += NT) {
            int k = idx / N_, i = idx % N_;
            g_W1t[idx] = W1[i * H_ + k];
            g_b1t[idx] = b1[i * H_ + k];
        }
        for (int idx = t; idx < 2 * H_ * N_; idx += NT) {
            int o = idx / N_, i = idx % N_;   // o = c*32+h
            g_W2t[idx] = W2[i * 2 * H_ + o];
        }
        for (int idx = t; idx < 2 * N_; idx += NT) {
            int o = idx / N_, i = idx % N_;
            g_b2t[idx] = b2[i * 2 + o];
        }
    }
}

// ---------------------------------------------------------------
// GEMM: C[b][i] = sum_k act[b][k] * effw[i][k], split-K partials.
// grid = (4 i-tiles, 4 b-tiles, 16 k-chunks), 256 threads, 64x64 tile,
// 4x4 register blocking. Blocks (y==0,z==0) also compute g_bias.
// ---------------------------------------------------------------
__global__ __launch_bounds__(256, 2)
void gemm_kernel(const float* __restrict__ adj,
                 const float* __restrict__ b_pw)
{
    __shared__ float As[KT][64];   // [k][b]
    __shared__ float Bs[KT][64];   // [k][i]

    const int tid = threadIdx.x;
    const int i0  = blockIdx.x * 64;
    const int b0  = blockIdx.y * 64;
    const int kc0 = blockIdx.z * KC;

    const int tx = tid & 15;   // i direction (4 elems)
    const int ty = tid >> 4;   // b direction (4 elems)

    const int lr = tid >> 2;   // load row 0..63
    const int lc = tid & 3;    // float4 column 0..3

    float acc[4][4] = {};

    for (int kt = 0; kt < KC; kt += KT) {
        const int kb = kc0 + kt;
        float4 av = *reinterpret_cast<const float4*>(&g_act [(b0 + lr) * K_ + kb + lc * 4]);
        float4 bv = *reinterpret_cast<const float4*>(&g_effw[(i0 + lr) * K_ + kb + lc * 4]);
        __syncthreads();
        As[lc * 4 + 0][lr] = av.x; As[lc * 4 + 1][lr] = av.y;
        As[lc * 4 + 2][lr] = av.z; As[lc * 4 + 3][lr] = av.w;
        Bs[lc * 4 + 0][lr] = bv.x; Bs[lc * 4 + 1][lr] = bv.y;
        Bs[lc * 4 + 2][lr] = bv.z; Bs[lc * 4 + 3][lr] = bv.w;
        __syncthreads();

        #pragma unroll
        for (int k = 0; k < KT; ++k) {
            float4 a4 = *reinterpret_cast<const float4*>(&As[k][ty * 4]);
            float4 b4 = *reinterpret_cast<const float4*>(&Bs[k][tx * 4]);
            acc[0][0] = fmaf(a4.x, b4.x, acc[0][0]);
            acc[0][1] = fmaf(a4.x, b4.y, acc[0][1]);
            acc[0][2] = fmaf(a4.x, b4.z, acc[0][2]);
            acc[0][3] = fmaf(a4.x, b4.w, acc[0][3]);
            acc[1][0] = fmaf(a4.y, b4.x, acc[1][0]);
            acc[1][1] = fmaf(a4.y, b4.y, acc[1][1]);
            acc[1][2] = fmaf(a4.y, b4.z, acc[1][2]);
            acc[1][3] = fmaf(a4.y, b4.w, acc[1][3]);
            acc[2][0] = fmaf(a4.z, b4.x, acc[2][0]);
            acc[2][1] = fmaf(a4.z, b4.y, acc[2][1]);
            acc[2][2] = fmaf(a4.z, b4.z, acc[2][2]);
            acc[2][3] = fmaf(a4.z, b4.w, acc[2][3]);
            acc[3][0] = fmaf(a4.w, b4.x, acc[3][0]);
            acc[3][1] = fmaf(a4.w, b4.y, acc[3][1]);
            acc[3][2] = fmaf(a4.w, b4.z, acc[3][2]);
            acc[3][3] = fmaf(a4.w, b4.w, acc[3][3]);
        }
    }

    float* dst = g_part[blockIdx.z];
    #pragma unroll
    for (int u = 0; u < 4; ++u) {
        float4 v = make_float4(acc[u][0], acc[u][1], acc[u][2], acc[u][3]);
        *reinterpret_cast<float4*>(&dst[(b0 + ty * 4 + u) * N_ + i0 + tx * 4]) = v;
    }

    // ---- bias[i] = sum_j eff(i,j) * b_pw[i,j], computed by 4 blocks ----
    if (blockIdx.y == 0 && blockIdx.z == 0) {
        const int i    = i0 + (tid >> 2);     // 64 i per block, 4 threads each
        const int part = tid & 3;
        const float* bpr = b_pw + (size_t)i * N_;
        float s = 0.f;
        #pragma unroll 4
        for (int jo = 0; jo < 64; ++jo) {
            int j = part * 64 + jo;
            float e = adj[j * N_ + i];
            float eff = (e > THRESH_ && i != j) ? e : 0.f;
            s = fmaf(eff, bpr[j], s);
        }
        s += __shfl_xor_sync(0xFFFFFFFFu, s, 1);
        s += __shfl_xor_sync(0xFFFFFFFFu, s, 2);
        if (part == 0) g_bias[i] = s;
    }
}

// ---------------------------------------------------------------
// epilogue: reduce split-K partials + per-node MLP, fully coalesced.
// ---------------------------------------------------------------
__global__ __launch_bounds__(256)
void epi_kernel(float* __restrict__ out)
{
    const int b = blockIdx.x;
    const int i = threadIdx.x;

    float c = g_bias[i];
    #pragma unroll
    for (int s = 0; s < SPLITK; ++s)
        c += g_part[s][b * N_ + i];

    float m  = g_b2t[i];
    float sd = g_b2t[N_ + i];
    #pragma unroll
    for (int k = 0; k < H_; ++k) {
        float h = fmaxf(fmaf(c, g_W1t[k * N_ + i], g_b1t[k * N_ + i]), 0.f);
        m  = fmaf(g_W2t[k * N_ + i],        h, m);
        sd = fmaf(g_W2t[(H_ + k) * N_ + i], h, sd);
    }
    out[b * N_ + i]                   = m;
    out[(size_t)B_ * N_ + b * N_ + i] = sd;
}

extern "C" void kernel_launch(void* const* d_in, const int* in_sizes, int n_in,
                              void* d_out, int out_size)
{
    const float* x    = (const float*)d_in[0];
    const float* adj  = (const float*)d_in[1];
    const float* bp   = (const float*)d_in[2];
    const float* w_pw = (const float*)d_in[3];
    const float* b_pw = (const float*)d_in[4];
    const float* W1   = (const float*)d_in[5];
    const float* b1   = (const float*)d_in[6];
    const float* W2   = (const float*)d_in[7];
    const float* b2   = (const float*)d_in[8];
    float* out = (float*)d_out;

    prep_kernel<<<FLAT_BLOCKS + WT_BLOCKS, 256>>>(x, adj, bp, w_pw, W1, b1, W2, b2);
    gemm_kernel<<<dim3(4, 4, SPLITK), 256>>>(adj, b_pw);
    epi_kernel<<<B_, 256>>>(out);
}